// round 1
// baseline (speedup 1.0000x reference)
#include <cuda_runtime.h>
#include <cuda_bf16.h>

// Problem constants (fixed by the reference setup)
#define E_EXPERTS 8
#define H_DIM 2048
#define I_DIM 1024
#define T_TOK 16384

// Scratch for intermediates (allocation-free rule: __device__ globals)
__device__ float g_scratch[(size_t)T_TOK * I_DIM];
__device__ float u_scratch[(size_t)T_TOK * I_DIM];

// -----------------------------------------------------------------------------
// Grouped GEMM: C[t, n] = sum_k A[t, k] * W[expert(t), k, n]
// A: [T, K] row-major. W: [E, K, N] row-major per expert. C: [T, N].
// Rows are contiguous per-expert blocks given by group_sizes (prefix-scanned
// in-kernel). Each block computes a 128x128 tile; if the tile straddles an
// expert boundary it loops over segments (never happens for these sizes but
// kept for correctness in general).
// Block: 256 threads, each owns an 8x8 micro-tile split as 2x(4 rows) x 2x(4 cols)
// for conflict-free float4 shared loads.
// -----------------------------------------------------------------------------
__global__ __launch_bounds__(256, 2)
void grouped_gemm_kernel(const float* __restrict__ A,
                         const float* __restrict__ W,
                         const int* __restrict__ group_sizes,
                         float* __restrict__ C,
                         int K, int N) {
    __shared__ float As[16][128];   // As[k][m] (transposed on store)
    __shared__ float Bs[16][128];   // Bs[k][n]
    __shared__ int bound[E_EXPERTS + 1];

    const int tid = threadIdx.x;
    if (tid == 0) {
        int acc = 0;
        bound[0] = 0;
        #pragma unroll
        for (int e = 0; e < E_EXPERTS; e++) { acc += group_sizes[e]; bound[e + 1] = acc; }
    }
    __syncthreads();

    const int m0 = blockIdx.y * 128;
    const int n0 = blockIdx.x * 128;
    const int ty = tid >> 4;   // 0..15
    const int tx = tid & 15;   // 0..15

    int row = m0;
    const int tile_end = m0 + 128;

    while (row < tile_end) {
        // expert owning 'row'
        int e = 0;
        while (bound[e + 1] <= row) e++;
        const int seg_end = (tile_end < bound[e + 1]) ? tile_end : bound[e + 1];
        const float* B = W + (size_t)e * K * N;

        float acc[8][8];
        #pragma unroll
        for (int i = 0; i < 8; i++)
            #pragma unroll
            for (int j = 0; j < 8; j++) acc[i][j] = 0.f;

        for (int k0 = 0; k0 < K; k0 += 16) {
            // Load A tile 128x16, store transposed As[k][m]
            #pragma unroll
            for (int l = 0; l < 2; l++) {
                int id = tid + l * 256;
                int r  = id >> 2;          // 0..127
                int c  = (id & 3) << 2;    // 0,4,8,12
                float4 v = *(const float4*)(A + (size_t)(m0 + r) * K + k0 + c);
                As[c + 0][r] = v.x;
                As[c + 1][r] = v.y;
                As[c + 2][r] = v.z;
                As[c + 3][r] = v.w;
            }
            // Load B tile 16x128 directly
            #pragma unroll
            for (int l = 0; l < 2; l++) {
                int id = tid + l * 256;
                int r  = id >> 5;          // 0..15
                int c  = (id & 31) << 2;   // 0..124
                *(float4*)(&Bs[r][c]) = *(const float4*)(B + (size_t)(k0 + r) * N + n0 + c);
            }
            __syncthreads();

            #pragma unroll
            for (int kk = 0; kk < 16; kk++) {
                float a[8], b[8];
                *(float4*)&a[0] = *(const float4*)&As[kk][ty * 4];
                *(float4*)&a[4] = *(const float4*)&As[kk][64 + ty * 4];
                *(float4*)&b[0] = *(const float4*)&Bs[kk][tx * 4];
                *(float4*)&b[4] = *(const float4*)&Bs[kk][64 + tx * 4];
                #pragma unroll
                for (int i = 0; i < 8; i++)
                    #pragma unroll
                    for (int j = 0; j < 8; j++)
                        acc[i][j] += a[i] * b[j];
            }
            __syncthreads();
        }

        // Write back rows within this expert segment
        #pragma unroll
        for (int i = 0; i < 8; i++) {
            int r = m0 + ((i < 4) ? (ty * 4 + i) : (64 + ty * 4 + (i - 4)));
            if (r >= row && r < seg_end) {
                *(float4*)(C + (size_t)r * N + n0 + tx * 4) =
                    make_float4(acc[i][0], acc[i][1], acc[i][2], acc[i][3]);
                *(float4*)(C + (size_t)r * N + n0 + 64 + tx * 4) =
                    make_float4(acc[i][4], acc[i][5], acc[i][6], acc[i][7]);
            }
        }
        row = seg_end;
    }
}

// h = silu(g) * u, written back into g
__global__ void swiglu_kernel(const float* g, const float* u, float* h, int n4) {
    int i = blockIdx.x * blockDim.x + threadIdx.x;
    if (i < n4) {
        float4 gv = ((const float4*)g)[i];
        float4 uv = ((const float4*)u)[i];
        float4 r;
        r.x = gv.x / (1.f + __expf(-gv.x)) * uv.x;
        r.y = gv.y / (1.f + __expf(-gv.y)) * uv.y;
        r.z = gv.z / (1.f + __expf(-gv.z)) * uv.z;
        r.w = gv.w / (1.f + __expf(-gv.w)) * uv.w;
        ((float4*)h)[i] = r;
    }
}

extern "C" void kernel_launch(void* const* d_in, const int* in_sizes, int n_in,
                              void* d_out, int out_size) {
    (void)in_sizes; (void)n_in; (void)out_size;
    const float* hidden = (const float*)d_in[0];
    const float* gate_w = (const float*)d_in[1];
    const float* up_w   = (const float*)d_in[2];
    const float* down_w = (const float*)d_in[3];
    const int*   gs     = (const int*)d_in[4];
    float* out = (float*)d_out;

    float *g_ptr, *u_ptr;
    cudaGetSymbolAddress((void**)&g_ptr, g_scratch);
    cudaGetSymbolAddress((void**)&u_ptr, u_scratch);

    dim3 grid_gu(I_DIM / 128, T_TOK / 128);   // (8, 128)
    grouped_gemm_kernel<<<grid_gu, 256>>>(hidden, gate_w, gs, g_ptr, H_DIM, I_DIM);
    grouped_gemm_kernel<<<grid_gu, 256>>>(hidden, up_w,   gs, u_ptr, H_DIM, I_DIM);

    int n4 = (T_TOK * I_DIM) / 4;             // 4,194,304
    swiglu_kernel<<<n4 / 256, 256>>>(g_ptr, u_ptr, g_ptr, n4);

    dim3 grid_dn(H_DIM / 128, T_TOK / 128);   // (16, 128)
    grouped_gemm_kernel<<<grid_dn, 256>>>(g_ptr, down_w, gs, out, I_DIM, H_DIM);
}

// round 3
// speedup vs baseline: 2.7244x; 2.7244x over previous
#include <cuda_runtime.h>
#include <cuda_bf16.h>
#include <cstdint>

#define E_EXPERTS 8
#define H_DIM 2048
#define I_DIM 1024
#define T_TOK 16384

// ---------------- device scratch (allocation-free rule) ----------------
__device__ float a_tf32[(size_t)T_TOK * H_DIM];    // rna-rounded activations
__device__ float h_scratch[(size_t)T_TOK * I_DIM]; // swiglu output (rna-rounded)

// ---------------- helpers ----------------
__device__ __forceinline__ float rna_tf32(float x) {
    uint32_t o;
    asm("cvt.rna.tf32.f32 %0, %1;" : "=r"(o) : "f"(x));
    return __uint_as_float(o);
}
__device__ __forceinline__ uint32_t rna_tf32_u(float x) {
    uint32_t o;
    asm("cvt.rna.tf32.f32 %0, %1;" : "=r"(o) : "f"(x));
    return o;
}
__device__ __forceinline__ uint32_t smem_u32(const void* p) {
    return (uint32_t)__cvta_generic_to_shared(p);
}
__device__ __forceinline__ void cp_async16(uint32_t dst, const void* src) {
    asm volatile("cp.async.cg.shared.global [%0], [%1], 16;" :: "r"(dst), "l"(src) : "memory");
}
__device__ __forceinline__ void mma_tf32(float* d, const uint32_t* a, const uint32_t* b) {
    asm volatile(
        "mma.sync.aligned.m16n8k8.row.col.f32.tf32.tf32.f32 "
        "{%0,%1,%2,%3}, {%4,%5,%6,%7}, {%8,%9}, {%0,%1,%2,%3};"
        : "+f"(d[0]), "+f"(d[1]), "+f"(d[2]), "+f"(d[3])
        : "r"(a[0]), "r"(a[1]), "r"(a[2]), "r"(a[3]), "r"(b[0]), "r"(b[1]));
}

// ---------------- prepass: rna-round activations ----------------
__global__ void round_a_kernel(const float4* __restrict__ in, float4* __restrict__ out, int n4) {
    int i = blockIdx.x * blockDim.x + threadIdx.x;
    if (i < n4) {
        float4 v = in[i];
        v.x = rna_tf32(v.x); v.y = rna_tf32(v.y);
        v.z = rna_tf32(v.z); v.w = rna_tf32(v.w);
        out[i] = v;
    }
}

// -----------------------------------------------------------------------------
// Grouped GEMM via mma.sync tf32 (HMMA tensor pipe).
// C[m,n] = sum_k A[m,k] * B[expert(m)][k,n]  (weights read natively, no transpose)
// NB==2: B1 also computed on the shared A frags; epilogue stores rna(silu(g)*u).
// CTA: BM=128 x BN, 256 threads (8 warps: 4 along M x 2 along N), BK=32, 4 stages.
// -----------------------------------------------------------------------------
template <int BN, int WN, int NB>
__global__ __launch_bounds__(256, 1)
void mma_gemm(const float* __restrict__ A, const float* __restrict__ B0,
              const float* __restrict__ B1, const int* __restrict__ gsz,
              float* __restrict__ C, int K, int N) {
    constexpr int BM = 128, BK = 32, S = 4;
    constexpr int APAD = 36;            // conflict-free A-fragment LDS
    constexpr int BPAD = BN + 8;        // conflict-free B-fragment LDS
    constexpr int A_FL = BM * APAD;     // floats per A stage
    constexpr int B_FL = BK * BPAD;     // floats per B stage (per matrix)
    constexpr int STAGE = A_FL + NB * B_FL;
    constexpr int WNA = WN / 8;         // n-atoms per warp per matrix
    constexpr int BCH = (BK * (BN / 4)) / 256;  // 16B chunks per thread per B matrix

    extern __shared__ float sm[];
    __shared__ int bound[E_EXPERTS + 1];

    const int tid = threadIdx.x;
    const int wid = tid >> 5;
    const int lane = tid & 31;
    const int wm = wid & 3;             // warp row block (32 rows)
    const int wn = wid >> 2;            // warp col block (WN cols)
    const int lr = lane >> 2;           // 0..7
    const int lc = lane & 3;            // 0..3

    if (tid < 32) {
        // warp 0 computes prefix bounds (redundant per lane, cheap)
        int acc = 0;
        if (lane == 0) {
            bound[0] = 0;
            #pragma unroll
            for (int e = 0; e < E_EXPERTS; e++) { acc += gsz[e]; bound[e + 1] = acc; }
        }
    }
    __syncthreads();

    const int m0 = blockIdx.y * BM;
    const int n0 = blockIdx.x * BN;
    const int nch = K / BK;

    int row = m0;
    while (row < m0 + BM) {
        int e = 0;
        while (bound[e + 1] <= row) e++;
        const int seg_end = bound[e + 1] < m0 + BM ? bound[e + 1] : m0 + BM;
        const float* Bg[2];
        Bg[0] = B0 + (size_t)e * K * N;
        Bg[1] = (NB == 2) ? (B1 + (size_t)e * K * N) : Bg[0];

        float acc[NB][2][WNA][4];
        #pragma unroll
        for (int j = 0; j < NB; j++)
            #pragma unroll
            for (int ma = 0; ma < 2; ma++)
                #pragma unroll
                for (int na = 0; na < WNA; na++)
                    #pragma unroll
                    for (int q = 0; q < 4; q++) acc[j][ma][na][q] = 0.f;

        auto load_stage = [&](int c) {
            int s = c & (S - 1);
            float* as = sm + s * STAGE;
            int kc = c * BK;
            #pragma unroll
            for (int i = 0; i < 4; i++) {
                int idx = tid + i * 256;
                int m = idx >> 3, kq = (idx & 7) << 2;
                cp_async16(smem_u32(as + m * APAD + kq),
                           A + (size_t)(m0 + m) * K + kc + kq);
            }
            #pragma unroll
            for (int j = 0; j < NB; j++) {
                float* bs = as + A_FL + j * B_FL;
                #pragma unroll
                for (int i = 0; i < BCH; i++) {
                    int idx = tid + i * 256;
                    int kr = idx / (BN / 4), nq = (idx % (BN / 4)) << 2;
                    cp_async16(smem_u32(bs + kr * BPAD + nq),
                               Bg[j] + (size_t)(kc + kr) * N + n0 + nq);
                }
            }
            asm volatile("cp.async.commit_group;" ::: "memory");
        };

        #pragma unroll
        for (int c = 0; c < S - 1; c++) load_stage(c);

        for (int c = 0; c < nch; c++) {
            asm volatile("cp.async.wait_group %0;" :: "n"(S - 2));
            __syncthreads();
            if (c + S - 1 < nch) load_stage(c + S - 1);
            else asm volatile("cp.async.commit_group;" ::: "memory");

            const float* as = sm + (c & (S - 1)) * STAGE;
            #pragma unroll
            for (int ks = 0; ks < 4; ks++) {
                const int k0 = ks * 8;
                uint32_t af[2][4];
                #pragma unroll
                for (int ma = 0; ma < 2; ma++) {
                    int rb = wm * 32 + ma * 16 + lr;
                    af[ma][0] = __float_as_uint(as[(size_t)rb * APAD + k0 + lc]);
                    af[ma][1] = __float_as_uint(as[(size_t)(rb + 8) * APAD + k0 + lc]);
                    af[ma][2] = __float_as_uint(as[(size_t)rb * APAD + k0 + lc + 4]);
                    af[ma][3] = __float_as_uint(as[(size_t)(rb + 8) * APAD + k0 + lc + 4]);
                }
                #pragma unroll
                for (int j = 0; j < NB; j++) {
                    const float* bs = as + A_FL + j * B_FL;
                    #pragma unroll
                    for (int na = 0; na < WNA; na++) {
                        int cb = wn * WN + na * 8 + lr;
                        uint32_t bf[2];
                        bf[0] = rna_tf32_u(bs[(size_t)(k0 + lc) * BPAD + cb]);
                        bf[1] = rna_tf32_u(bs[(size_t)(k0 + lc + 4) * BPAD + cb]);
                        #pragma unroll
                        for (int ma = 0; ma < 2; ma++)
                            mma_tf32(acc[j][ma][na], af[ma], bf);
                    }
                }
            }
            __syncthreads();
        }

        // ---------------- epilogue ----------------
        #pragma unroll
        for (int ma = 0; ma < 2; ma++) {
            int r1 = m0 + wm * 32 + ma * 16 + lr;
            int r2 = r1 + 8;
            bool a1 = (r1 >= row && r1 < seg_end);
            bool a2 = (r2 >= row && r2 < seg_end);
            #pragma unroll
            for (int na = 0; na < WNA; na++) {
                int col = n0 + wn * WN + na * 8 + 2 * lc;
                if (NB == 2) {
                    float g0 = acc[0][ma][na][0], g1 = acc[0][ma][na][1];
                    float g2 = acc[0][ma][na][2], g3 = acc[0][ma][na][3];
                    float u0 = acc[1][ma][na][0], u1 = acc[1][ma][na][1];
                    float u2 = acc[1][ma][na][2], u3 = acc[1][ma][na][3];
                    if (a1) {
                        float2 o;
                        o.x = rna_tf32(g0 / (1.f + __expf(-g0)) * u0);
                        o.y = rna_tf32(g1 / (1.f + __expf(-g1)) * u1);
                        *(float2*)(C + (size_t)r1 * N + col) = o;
                    }
                    if (a2) {
                        float2 o;
                        o.x = rna_tf32(g2 / (1.f + __expf(-g2)) * u2);
                        o.y = rna_tf32(g3 / (1.f + __expf(-g3)) * u3);
                        *(float2*)(C + (size_t)r2 * N + col) = o;
                    }
                } else {
                    if (a1)
                        *(float2*)(C + (size_t)r1 * N + col) =
                            make_float2(acc[0][ma][na][0], acc[0][ma][na][1]);
                    if (a2)
                        *(float2*)(C + (size_t)r2 * N + col) =
                            make_float2(acc[0][ma][na][2], acc[0][ma][na][3]);
                }
            }
        }
        row = seg_end;
    }
}

// ---------------- launch ----------------
extern "C" void kernel_launch(void* const* d_in, const int* in_sizes, int n_in,
                              void* d_out, int out_size) {
    (void)in_sizes; (void)n_in; (void)out_size;
    const float* hidden = (const float*)d_in[0];
    const float* gate_w = (const float*)d_in[1];
    const float* up_w   = (const float*)d_in[2];
    const float* down_w = (const float*)d_in[3];
    const int*   gs     = (const int*)d_in[4];
    float* out = (float*)d_out;

    float *aP, *hP;
    cudaGetSymbolAddress((void**)&aP, a_tf32);
    cudaGetSymbolAddress((void**)&hP, h_scratch);

    // smem: fused = 4*(128*36 + 2*32*72)*4 = 147456 B; down = 4*(128*36 + 32*136)*4 = 143360 B
    constexpr int SMEM_FUSED = 4 * (128 * 36 + 2 * 32 * 72) * 4;
    constexpr int SMEM_DOWN  = 4 * (128 * 36 + 32 * 136) * 4;
    cudaFuncSetAttribute((const void*)mma_gemm<64, 32, 2>,
                         cudaFuncAttributeMaxDynamicSharedMemorySize, SMEM_FUSED);
    cudaFuncSetAttribute((const void*)mma_gemm<128, 64, 1>,
                         cudaFuncAttributeMaxDynamicSharedMemorySize, SMEM_DOWN);

    int n4 = (int)((size_t)T_TOK * H_DIM / 4);
    round_a_kernel<<<(n4 + 255) / 256, 256>>>((const float4*)hidden, (float4*)aP, n4);

    // fused gate/up + SwiGLU -> h   (A=[T,H], B=[H,I])
    mma_gemm<64, 32, 2><<<dim3(I_DIM / 64, T_TOK / 128), 256, SMEM_FUSED>>>(
        aP, gate_w, up_w, gs, hP, H_DIM, I_DIM);
    // down projection -> out        (A=[T,I], B=[I,H])
    mma_gemm<128, 64, 1><<<dim3(H_DIM / 128, T_TOK / 128), 256, SMEM_DOWN>>>(
        hP, down_w, nullptr, gs, out, I_DIM, H_DIM);
}

// round 4
// speedup vs baseline: 3.3181x; 1.2179x over previous
#include <cuda_runtime.h>
#include <cuda_bf16.h>
#include <cstdint>

#define E_EXPERTS 8
#define H_DIM 2048
#define I_DIM 1024
#define T_TOK 16384

// ---------------- device scratch (allocation-free rule) ----------------
__device__ float a_tf32[(size_t)T_TOK * H_DIM];                 // rna-rounded activations
__device__ float h_scratch[(size_t)T_TOK * I_DIM];              // swiglu output (rounded)
__device__ float gate_r[(size_t)E_EXPERTS * H_DIM * I_DIM];     // rna-rounded weights
__device__ float up_r[(size_t)E_EXPERTS * H_DIM * I_DIM];
__device__ float down_r[(size_t)E_EXPERTS * H_DIM * I_DIM];

// ---------------- helpers ----------------
__device__ __forceinline__ float rna_tf32(float x) {
    uint32_t o;
    asm("cvt.rna.tf32.f32 %0, %1;" : "=r"(o) : "f"(x));
    return __uint_as_float(o);
}
__device__ __forceinline__ uint32_t smem_u32(const void* p) {
    return (uint32_t)__cvta_generic_to_shared(p);
}
__device__ __forceinline__ void cp_async16(uint32_t dst, const void* src) {
    asm volatile("cp.async.cg.shared.global [%0], [%1], 16;" :: "r"(dst), "l"(src) : "memory");
}
__device__ __forceinline__ void mma_tf32(float* d, const uint32_t* a, const uint32_t* b) {
    asm volatile(
        "mma.sync.aligned.m16n8k8.row.col.f32.tf32.tf32.f32 "
        "{%0,%1,%2,%3}, {%4,%5,%6,%7}, {%8,%9}, {%0,%1,%2,%3};"
        : "+f"(d[0]), "+f"(d[1]), "+f"(d[2]), "+f"(d[3])
        : "r"(a[0]), "r"(a[1]), "r"(a[2]), "r"(a[3]), "r"(b[0]), "r"(b[1]));
}

// ---------------- prepass: rna-round (elementwise) ----------------
__global__ void round_kernel(const float4* __restrict__ in, float4* __restrict__ out, int n4) {
    int i = blockIdx.x * blockDim.x + threadIdx.x;
    if (i < n4) {
        float4 v = in[i];
        v.x = rna_tf32(v.x); v.y = rna_tf32(v.y);
        v.z = rna_tf32(v.z); v.w = rna_tf32(v.w);
        out[i] = v;
    }
}

// -----------------------------------------------------------------------------
// Grouped GEMM via mma.sync tf32 (HMMA).
// C[m,n] = sum_k A[m,k] * B[expert(m)][k,n]; all operands pre-rounded to tf32.
// CTA 128x128 (per matrix), 256 threads = 8 warps (2 along M x 4 along N),
// warp tile 64x32 per matrix (ma=4, na=4). BK=32, S-stage cp.async ring,
// ONE __syncthreads per chunk (ring safety: writes target stage (c-1) mod S).
// NB==2: gate+up fused on shared A frags; epilogue stores rna(silu(g)*u).
// -----------------------------------------------------------------------------
template <int NB, int S>
__global__ __launch_bounds__(256, NB == 1 ? 2 : 1)
void mma_gemm(const float* __restrict__ A, const float* __restrict__ B0,
              const float* __restrict__ B1, const int* __restrict__ gsz,
              float* __restrict__ C, int K, int N) {
    constexpr int BM = 128, BN = 128, BK = 32;
    constexpr int APAD = 36;
    constexpr int BPAD = BN + 8;            // 136
    constexpr int A_FL = BM * APAD;         // 4608
    constexpr int B_FL = BK * BPAD;         // 4352
    constexpr int STAGE = A_FL + NB * B_FL;

    extern __shared__ float sm[];
    __shared__ int bound[E_EXPERTS + 1];

    const int tid = threadIdx.x;
    const int wid = tid >> 5;
    const int lane = tid & 31;
    const int wm = wid & 1;                 // 2 warp-rows of 64
    const int wn = wid >> 1;                // 4 warp-cols of 32
    const int lr = lane >> 2;               // 0..7
    const int lc = lane & 3;                // 0..3

    if (tid == 0) {
        int acc = 0;
        bound[0] = 0;
        #pragma unroll
        for (int e = 0; e < E_EXPERTS; e++) { acc += gsz[e]; bound[e + 1] = acc; }
    }
    __syncthreads();

    const int m0 = blockIdx.y * BM;
    const int n0 = blockIdx.x * BN;
    const int nch = K / BK;

    int row = m0;
    while (row < m0 + BM) {
        int e = 0;
        while (bound[e + 1] <= row) e++;
        const int seg_end = bound[e + 1] < m0 + BM ? bound[e + 1] : m0 + BM;
        const float* Bg[2];
        Bg[0] = B0 + (size_t)e * K * N;
        Bg[1] = (NB == 2) ? (B1 + (size_t)e * K * N) : Bg[0];

        float acc[NB][4][4][4];             // [matrix][ma][na][quad]
        #pragma unroll
        for (int j = 0; j < NB; j++)
            #pragma unroll
            for (int ma = 0; ma < 4; ma++)
                #pragma unroll
                for (int na = 0; na < 4; na++)
                    #pragma unroll
                    for (int q = 0; q < 4; q++) acc[j][ma][na][q] = 0.f;

        auto load_stage = [&](int c) {
            int s = c % S;
            float* as = sm + s * STAGE;
            int kc = c * BK;
            #pragma unroll
            for (int i = 0; i < 4; i++) {
                int idx = tid + i * 256;
                int m = idx >> 3, kq = (idx & 7) << 2;
                cp_async16(smem_u32(as + m * APAD + kq),
                           A + (size_t)(m0 + m) * K + kc + kq);
            }
            #pragma unroll
            for (int j = 0; j < NB; j++) {
                float* bs = as + A_FL + j * B_FL;
                #pragma unroll
                for (int i = 0; i < 4; i++) {
                    int idx = tid + i * 256;
                    int kr = idx >> 5, nq = (idx & 31) << 2;
                    cp_async16(smem_u32(bs + kr * BPAD + nq),
                               Bg[j] + (size_t)(kc + kr) * N + n0 + nq);
                }
            }
            asm volatile("cp.async.commit_group;" ::: "memory");
        };

        #pragma unroll
        for (int c = 0; c < S - 1; c++) load_stage(c);

        for (int c = 0; c < nch; c++) {
            asm volatile("cp.async.wait_group %0;" :: "n"(S - 2));
            __syncthreads();
            if (c + S - 1 < nch) load_stage(c + S - 1);
            else asm volatile("cp.async.commit_group;" ::: "memory");

            const float* as = sm + (c % S) * STAGE;
            #pragma unroll
            for (int ks = 0; ks < 4; ks++) {
                const int k0 = ks * 8;
                uint32_t af[4][4];
                #pragma unroll
                for (int ma = 0; ma < 4; ma++) {
                    int rb = wm * 64 + ma * 16 + lr;
                    const float* ar = as + (size_t)rb * APAD + k0 + lc;
                    af[ma][0] = __float_as_uint(ar[0]);
                    af[ma][1] = __float_as_uint(ar[8 * APAD]);
                    af[ma][2] = __float_as_uint(ar[4]);
                    af[ma][3] = __float_as_uint(ar[8 * APAD + 4]);
                }
                #pragma unroll
                for (int j = 0; j < NB; j++) {
                    const float* bs = as + A_FL + j * B_FL;
                    #pragma unroll
                    for (int na = 0; na < 4; na++) {
                        int cb = wn * 32 + na * 8 + lr;
                        uint32_t bf[2];
                        bf[0] = __float_as_uint(bs[(size_t)(k0 + lc) * BPAD + cb]);
                        bf[1] = __float_as_uint(bs[(size_t)(k0 + lc + 4) * BPAD + cb]);
                        #pragma unroll
                        for (int ma = 0; ma < 4; ma++)
                            mma_tf32(acc[j][ma][na], af[ma], bf);
                    }
                }
            }
        }

        // ---------------- epilogue ----------------
        #pragma unroll
        for (int ma = 0; ma < 4; ma++) {
            int r1 = m0 + wm * 64 + ma * 16 + lr;
            int r2 = r1 + 8;
            bool a1 = (r1 >= row && r1 < seg_end);
            bool a2 = (r2 >= row && r2 < seg_end);
            #pragma unroll
            for (int na = 0; na < 4; na++) {
                int col = n0 + wn * 32 + na * 8 + 2 * lc;
                if (NB == 2) {
                    float g0 = acc[0][ma][na][0], g1 = acc[0][ma][na][1];
                    float g2 = acc[0][ma][na][2], g3 = acc[0][ma][na][3];
                    float u0 = acc[1][ma][na][0], u1 = acc[1][ma][na][1];
                    float u2 = acc[1][ma][na][2], u3 = acc[1][ma][na][3];
                    if (a1) {
                        float2 o;
                        o.x = rna_tf32(g0 / (1.f + __expf(-g0)) * u0);
                        o.y = rna_tf32(g1 / (1.f + __expf(-g1)) * u1);
                        *(float2*)(C + (size_t)r1 * N + col) = o;
                    }
                    if (a2) {
                        float2 o;
                        o.x = rna_tf32(g2 / (1.f + __expf(-g2)) * u2);
                        o.y = rna_tf32(g3 / (1.f + __expf(-g3)) * u3);
                        *(float2*)(C + (size_t)r2 * N + col) = o;
                    }
                } else {
                    if (a1)
                        *(float2*)(C + (size_t)r1 * N + col) =
                            make_float2(acc[0][ma][na][0], acc[0][ma][na][1]);
                    if (a2)
                        *(float2*)(C + (size_t)r2 * N + col) =
                            make_float2(acc[0][ma][na][2], acc[0][ma][na][3]);
                }
            }
        }
        __syncthreads();   // protect smem ring across segments / tail cp.asyncs
        row = seg_end;
    }
}

// ---------------- launch ----------------
extern "C" void kernel_launch(void* const* d_in, const int* in_sizes, int n_in,
                              void* d_out, int out_size) {
    (void)in_sizes; (void)n_in; (void)out_size;
    const float* hidden = (const float*)d_in[0];
    const float* gate_w = (const float*)d_in[1];
    const float* up_w   = (const float*)d_in[2];
    const float* down_w = (const float*)d_in[3];
    const int*   gs     = (const int*)d_in[4];
    float* out = (float*)d_out;

    float *aP, *hP, *gP, *uP, *dP;
    cudaGetSymbolAddress((void**)&aP, a_tf32);
    cudaGetSymbolAddress((void**)&hP, h_scratch);
    cudaGetSymbolAddress((void**)&gP, gate_r);
    cudaGetSymbolAddress((void**)&uP, up_r);
    cudaGetSymbolAddress((void**)&dP, down_r);

    // smem: fused S=4: 4*(4608+2*4352)*4 = 212992 B; down S=3: 3*(4608+4352)*4 = 107520 B
    constexpr int SMEM_FUSED = 4 * (4608 + 2 * 4352) * 4;
    constexpr int SMEM_DOWN  = 3 * (4608 + 4352) * 4;
    cudaFuncSetAttribute((const void*)mma_gemm<2, 4>,
                         cudaFuncAttributeMaxDynamicSharedMemorySize, SMEM_FUSED);
    cudaFuncSetAttribute((const void*)mma_gemm<1, 3>,
                         cudaFuncAttributeMaxDynamicSharedMemorySize, SMEM_DOWN);

    // prepass: rna-round activations + all weights (removes cvt from mainloops)
    int nA4 = (int)((size_t)T_TOK * H_DIM / 4);
    int nW4 = (int)((size_t)E_EXPERTS * H_DIM * I_DIM / 4);
    round_kernel<<<(nA4 + 255) / 256, 256>>>((const float4*)hidden, (float4*)aP, nA4);
    round_kernel<<<(nW4 + 255) / 256, 256>>>((const float4*)gate_w, (float4*)gP, nW4);
    round_kernel<<<(nW4 + 255) / 256, 256>>>((const float4*)up_w,   (float4*)uP, nW4);
    round_kernel<<<(nW4 + 255) / 256, 256>>>((const float4*)down_w, (float4*)dP, nW4);

    // fused gate/up + SwiGLU -> h   (A=[T,H], B=[H,I])
    mma_gemm<2, 4><<<dim3(I_DIM / 128, T_TOK / 128), 256, SMEM_FUSED>>>(
        aP, gP, uP, gs, hP, H_DIM, I_DIM);
    // down projection -> out        (A=[T,I], B=[I,H])
    mma_gemm<1, 3><<<dim3(H_DIM / 128, T_TOK / 128), 256, SMEM_DOWN>>>(
        hP, dP, nullptr, gs, out, I_DIM, H_DIM);
}